// round 13
// baseline (speedup 1.0000x reference)
#include <cuda_runtime.h>
#include <cuda_fp16.h>

// ---------------------------------------------------------------------------
// UMTP propagation, v13 = v9 (unroll-4, 1673us verified) with dual-edge
// gathers: lanes 0-15 fetch edge A's 128B row, lanes 16-31 edge B's row,
// one LDG.64 instruction per TWO edges (same bytes/wavefronts, half the
// instructions). Groups combined by shfl_xor(16); float4 accumulators.
// ---------------------------------------------------------------------------

#define NMAX     100000
#define EMAX     1600000
#define DATTR    50
#define D2       25
#define HPAD     32          // half2 per padded row (128 bytes = 16 x 8B)
#define NUM_ITER 30
#define WPB      8
#define SCANB    1024

__device__ int    g_deg[NMAX];
__device__ float  g_dinv[NMAX];
__device__ int    g_rowptr[NMAX + 1];
__device__ int    g_cursor[NMAX];
__device__ int    g_csrc[EMAX];        // cols only
__device__ unsigned char g_known[NMAX];
__device__ int    g_bsum[128];
__device__ int    g_boff[128];
__device__ __align__(16) float g_mean[64];
__device__ __align__(16) float g_alpha[64];
__device__ __align__(16) float g_beta[64];
__device__ __align__(16) float g_colsum[(NUM_ITER + 1) * 64];
__device__ __align__(128) __half2 g_hA[NMAX * HPAD];
__device__ __align__(128) __half2 g_hB[NMAX * HPAD];
__device__ float  g_xk[NMAX * DATTR];

// ---- 0) zero per-launch state ----
__global__ void zero_kernel(int n) {
    int i = blockIdx.x * blockDim.x + threadIdx.x;
    if (i < n) { g_deg[i] = 0; g_known[i] = 0; }
    if (i < 64) g_mean[i] = 0.0f;
    if (i < (NUM_ITER + 1) * 64) g_colsum[i] = 0.0f;
}

// ---- 1) out-degree histogram ----
__global__ void deg_kernel(const int* __restrict__ row, int e) {
    int j = blockIdx.x * blockDim.x + threadIdx.x;
    if (j < e) atomicAdd(&g_deg[row[j]], 1);
}

// ---- 2) dinv + alpha/beta (entries [d..63] padded: alpha=beta=1) ----
__global__ void dinv_alpha_kernel(const float* __restrict__ eta,
                                  const float* __restrict__ theta,
                                  int n, int d) {
    int i = blockIdx.x * blockDim.x + threadIdx.x;
    if (i < n) {
        int dg = g_deg[i];
        g_dinv[i] = (dg > 0) ? rsqrtf((float)dg) : 0.0f;
    }
    if (i < 64) {
        if (i < d) {
            float nf = (float)n;
            float a = (nf - 1.0f) / (theta[i] * nf + (nf - 1.0f));
            g_alpha[i] = a;
            float inva = 1.0f / a;
            g_beta[i] = inva / (inva + eta[i]);
        } else {
            g_alpha[i] = 1.0f;
            g_beta[i] = 1.0f;
        }
    }
}

// ---- 3a) per-block degree sums ----
__global__ void scan_sum_kernel(int n) {
    __shared__ int ssum;
    if (threadIdx.x == 0) ssum = 0;
    __syncthreads();
    int i = blockIdx.x * SCANB + threadIdx.x;
    int v = (i < n) ? g_deg[i] : 0;
    #pragma unroll
    for (int off = 16; off > 0; off >>= 1)
        v += __shfl_down_sync(0xffffffffu, v, off);
    if ((threadIdx.x & 31) == 0) atomicAdd(&ssum, v);
    __syncthreads();
    if (threadIdx.x == 0) g_bsum[blockIdx.x] = ssum;
}

// ---- 3b) scan block sums ----
__global__ void scan_top_kernel(int nb, int n) {
    __shared__ int s[128];
    int t = threadIdx.x;
    int v = (t < nb) ? g_bsum[t] : 0;
    s[t] = v;
    __syncthreads();
    #pragma unroll
    for (int off = 1; off < 128; off <<= 1) {
        int tv = (t >= off) ? s[t - off] : 0;
        __syncthreads();
        s[t] += tv;
        __syncthreads();
    }
    if (t < nb) g_boff[t] = s[t] - v;
    if (t == nb - 1) g_rowptr[n] = s[t];
}

// ---- 3c) per-block exclusive scan + offset ----
__global__ void scan_write_kernel(int n) {
    __shared__ int s[SCANB];
    int tid = threadIdx.x;
    int i = blockIdx.x * SCANB + tid;
    int v = (i < n) ? g_deg[i] : 0;
    s[tid] = v;
    __syncthreads();
    #pragma unroll
    for (int off = 1; off < SCANB; off <<= 1) {
        int tv = (tid >= off) ? s[tid - off] : 0;
        __syncthreads();
        s[tid] += tv;
        __syncthreads();
    }
    if (i < n) {
        int excl = g_boff[blockIdx.x] + s[tid] - v;
        g_rowptr[i] = excl;
        g_cursor[i] = excl;
    }
}

// ---- 4) scatter edge cols into CSR ----
__global__ void scatter_kernel(const int* __restrict__ row,
                               const int* __restrict__ col, int e) {
    int j = blockIdx.x * blockDim.x + threadIdx.x;
    if (j < e) {
        int r = row[j];
        int pos = atomicAdd(&g_cursor[r], 1);
        g_csrc[pos] = col[j];
    }
}

// ---- 5) known flags + mean sums ----
__global__ void mask_mean_kernel(const float* __restrict__ x,
                                 const int* __restrict__ mask, int kcnt) {
    int lane = threadIdx.x & 31;
    int wid = threadIdx.x >> 5;
    int gw = blockIdx.x * (blockDim.x >> 5) + wid;
    int nw = gridDim.x * (blockDim.x >> 5);
    const float2* x2 = (const float2*)x;
    float ax = 0.0f, ay = 0.0f;
    for (int j = gw; j < kcnt; j += nw) {
        int i = mask[j];
        if (lane == 0) g_known[i] = 1;
        if (lane < D2) {
            float2 v = __ldg(&x2[i * D2 + lane]);
            ax += v.x; ay += v.y;
        }
    }
    __shared__ float sm[64];
    if (threadIdx.x < 64) sm[threadIdx.x] = 0.0f;
    __syncthreads();
    if (lane < D2) {
        atomicAdd(&sm[2 * lane], ax);
        atomicAdd(&sm[2 * lane + 1], ay);
    }
    __syncthreads();
    if (threadIdx.x < DATTR) atomicAdd(&g_mean[threadIdx.x], sm[threadIdx.x]);
}

__global__ void mean_div_kernel(int kcnt) {
    if (threadIdx.x < DATTR) g_mean[threadIdx.x] *= (1.0f / (float)kcnt);
}

// ---- 6) xk = x - mean; hA = half(dinv*out0), pad lanes zeroed ----
__global__ void __launch_bounds__(256) init_kernel(const float* __restrict__ x, int n) {
    int lane = threadIdx.x & 31;
    int i = (blockIdx.x * blockDim.x + threadIdx.x) >> 5;
    float vx = 0.0f, vy = 0.0f;
    if (i < n) {
        if (lane < D2) {
            const float2* x2 = (const float2*)x;
            float2 xv = __ldg(&x2[i * D2 + lane]);
            float m0 = g_mean[2 * lane], m1 = g_mean[2 * lane + 1];
            float kx = xv.x - m0, ky = xv.y - m1;
            ((float2*)g_xk)[i * D2 + lane] = make_float2(kx, ky);
            if (g_known[i]) { vx = kx; vy = ky; }
            else            { vx = -m0; vy = -m1; }
            float di = g_dinv[i];
            g_hA[i * HPAD + lane] = __floats2half2_rn(di * vx, di * vy);
        } else {
            g_hA[i * HPAD + lane] = __floats2half2_rn(0.0f, 0.0f);
        }
    }
    __shared__ float sm[64];
    if (threadIdx.x < 64) sm[threadIdx.x] = 0.0f;
    __syncthreads();
    if (i < n && lane < D2) {
        atomicAdd(&sm[2 * lane], vx);
        atomicAdd(&sm[2 * lane + 1], vy);
    }
    __syncthreads();
    if (threadIdx.x < DATTR) atomicAdd(&g_colsum[threadIdx.x], sm[threadIdx.x]);
}

// ---- 7) propagation: dual-edge LDG.64 gathers, unroll-4 ----
__global__ void __launch_bounds__(256) spmm_kernel(
    const __half2* __restrict__ src, __half2* __restrict__ dst,
    float* __restrict__ dout,
    const float* __restrict__ colsum_in, float* __restrict__ colsum_out,
    int n, float inv_n, int final_add_mean) {

    int lane = threadIdx.x & 31;
    int g = lane >> 4;          // edge slot within pair
    int sl = lane & 15;         // 8B chunk within row (16 x 8B = 128B)
    int i = (blockIdx.x * blockDim.x + threadIdx.x) >> 5;
    bool valid = (i < n);
    float4 v4 = make_float4(0.0f, 0.0f, 0.0f, 0.0f);

    if (valid) {
        const uint2* s8 = (const uint2*)src;     // row i at i*16 (8B units)
        float4 acc = make_float4(0.0f, 0.0f, 0.0f, 0.0f);
        int jb = g_rowptr[i], je = g_rowptr[i + 1];
        int j = jb;
        if ((j & 1) && j < je) {                 // head: single edge, group 0
            int c = __ldg(&g_csrc[j]);
            if (g == 0) {
                uint2 u = __ldg(&s8[c * 16 + sl]);
                float2 lo = __half22float2(*(const __half2*)&u.x);
                float2 hi = __half22float2(*(const __half2*)&u.y);
                acc.x += lo.x; acc.y += lo.y; acc.z += hi.x; acc.w += hi.y;
            }
            j++;
        }
        const int2* csr2 = (const int2*)g_csrc;
        int p = j >> 1, pe = je >> 1;
        #pragma unroll 4
        for (; p < pe; p++) {
            int2 c01 = __ldg(&csr2[p]);
            int c = g ? c01.y : c01.x;
            uint2 u = __ldg(&s8[c * 16 + sl]);
            float2 lo = __half22float2(*(const __half2*)&u.x);
            float2 hi = __half22float2(*(const __half2*)&u.y);
            acc.x += lo.x; acc.y += lo.y; acc.z += hi.x; acc.w += hi.y;
        }
        j = pe << 1;
        if (j < je) {                            // tail: single edge, group 0
            int c = __ldg(&g_csrc[j]);
            if (g == 0) {
                uint2 u = __ldg(&s8[c * 16 + sl]);
                float2 lo = __half22float2(*(const __half2*)&u.x);
                float2 hi = __half22float2(*(const __half2*)&u.y);
                acc.x += lo.x; acc.y += lo.y; acc.z += hi.x; acc.w += hi.y;
            }
        }
        // combine the two edge groups
        acc.x += __shfl_xor_sync(0xffffffffu, acc.x, 16);
        acc.y += __shfl_xor_sync(0xffffffffu, acc.y, 16);
        acc.z += __shfl_xor_sync(0xffffffffu, acc.z, 16);
        acc.w += __shfl_xor_sync(0xffffffffu, acc.w, 16);

        if (lane < 16) {
            float di = g_dinv[i];
            acc.x *= di; acc.y *= di; acc.z *= di; acc.w *= di;
            int d0 = 4 * sl;                     // attrs [d0, d0+4)
            float4 al = *(const float4*)&g_alpha[d0];
            float4 cm = *(const float4*)&colsum_in[d0];
            v4.x = al.x * acc.x + (1.0f - al.x) * (cm.x * inv_n);
            v4.y = al.y * acc.y + (1.0f - al.y) * (cm.y * inv_n);
            v4.z = al.z * acc.z + (1.0f - al.z) * (cm.z * inv_n);
            v4.w = al.w * acc.w + (1.0f - al.w) * (cm.w * inv_n);
            if (g_known[i]) {
                float4 be = *(const float4*)&g_beta[d0];
                float2 xk01 = make_float2(0.0f, 0.0f);
                float2 xk23 = make_float2(0.0f, 0.0f);
                const float2* xkp = (const float2*)(g_xk + i * DATTR + d0);
                if (sl < 12)       { xk01 = __ldg(&xkp[0]); xk23 = __ldg(&xkp[1]); }
                else if (sl == 12) { xk01 = __ldg(&xkp[0]); }
                v4.x = be.x * v4.x + (1.0f - be.x) * xk01.x;
                v4.y = be.y * v4.y + (1.0f - be.y) * xk01.y;
                v4.z = be.z * v4.z + (1.0f - be.z) * xk23.x;
                v4.w = be.w * v4.w + (1.0f - be.w) * xk23.y;
            }
            if (!final_add_mean) {
                __half2 h0 = __floats2half2_rn(di * v4.x, di * v4.y);
                __half2 h1 = __floats2half2_rn(di * v4.z, di * v4.w);
                uint2 u;
                u.x = *(const unsigned int*)&h0;
                u.y = *(const unsigned int*)&h1;
                ((uint2*)dst)[i * 16 + sl] = u;
            } else {
                float4 m = *(const float4*)&g_mean[d0];
                float2* op = (float2*)(dout + i * DATTR + d0);
                if (sl < 12) {
                    op[0] = make_float2(v4.x + m.x, v4.y + m.y);
                    op[1] = make_float2(v4.z + m.z, v4.w + m.w);
                } else if (sl == 12) {
                    op[0] = make_float2(v4.x + m.x, v4.y + m.y);
                }
            }
        }
    }

    if (!final_add_mean) {
        __shared__ float sm[64];
        if (threadIdx.x < 64) sm[threadIdx.x] = 0.0f;
        __syncthreads();
        if (valid && lane < 16) {
            int d0 = 4 * sl;
            atomicAdd(&sm[d0],     v4.x);
            atomicAdd(&sm[d0 + 1], v4.y);
            atomicAdd(&sm[d0 + 2], v4.z);
            atomicAdd(&sm[d0 + 3], v4.w);
        }
        __syncthreads();
        if (threadIdx.x < DATTR)
            atomicAdd(&colsum_out[threadIdx.x], sm[threadIdx.x]);
    }
}

// ---------------------------------------------------------------------------

extern "C" void kernel_launch(void* const* d_in, const int* in_sizes, int n_in,
                              void* d_out, int out_size) {
    const float* x     = (const float*)d_in[0];
    const float* eta   = (const float*)d_in[1];
    const float* theta = (const float*)d_in[2];
    const int*   ei    = (const int*)d_in[3];
    const int*   mask  = (const int*)d_in[4];

    const int D = in_sizes[1];        // 50
    const int n = in_sizes[0] / D;    // 100000
    const int e = in_sizes[3] / 2;    // 1600000
    const int k = in_sizes[4];        // 50000
    const int* row = ei;
    const int* col = ei + e;

    __half2 *hA, *hB;
    float *colsum;
    cudaGetSymbolAddress((void**)&hA, g_hA);
    cudaGetSymbolAddress((void**)&hB, g_hB);
    cudaGetSymbolAddress((void**)&colsum, g_colsum);

    int nb_scan = (n + SCANB - 1) / SCANB;   // 98

    zero_kernel<<<(n + 255) / 256, 256>>>(n);
    deg_kernel<<<(e + 255) / 256, 256>>>(row, e);
    dinv_alpha_kernel<<<(n + 255) / 256, 256>>>(eta, theta, n, D);
    scan_sum_kernel<<<nb_scan, SCANB>>>(n);
    scan_top_kernel<<<1, 128>>>(nb_scan, n);
    scan_write_kernel<<<nb_scan, SCANB>>>(n);
    scatter_kernel<<<(e + 255) / 256, 256>>>(row, col, e);
    mask_mean_kernel<<<64, 256>>>(x, mask, k);
    mean_div_kernel<<<1, 64>>>(k);

    int nblocks = (n + WPB - 1) / WPB;
    init_kernel<<<nblocks, 256>>>(x, n);

    float inv_n = 1.0f / (float)n;
    __half2* bufs[2] = { hA, hB };
    for (int t = 0; t < NUM_ITER; t++) {
        const __half2* src = bufs[t & 1];
        int is_final = (t == NUM_ITER - 1);
        __half2* dst = bufs[(t + 1) & 1];
        spmm_kernel<<<nblocks, 256>>>(src, dst, (float*)d_out,
                                      colsum + t * 64, colsum + (t + 1) * 64,
                                      n, inv_n, is_final);
    }
}

// round 16
// speedup vs baseline: 1.0479x; 1.0479x over previous
#include <cuda_runtime.h>
#include <cuda_fp16.h>

// ---------------------------------------------------------------------------
// UMTP propagation, v14 = v9 spmm EXACT (unroll-4, all-lane gathers, 1673us
// verified) + prologue tuning only:
//   - deg/scatter kernels vectorized int4 (4 edges/thread)
//   - mask_mean grid 64 -> 128 blocks
// ---------------------------------------------------------------------------

#define NMAX     100000
#define EMAX     1600000
#define DATTR    50
#define D2       25          // half2 / float2 data lanes per row
#define HPAD     32          // half2 per padded row (128 bytes)
#define NUM_ITER 30
#define WPB      8
#define SCANB    1024

__device__ int    g_deg[NMAX];
__device__ float  g_dinv[NMAX];
__device__ int    g_rowptr[NMAX + 1];
__device__ int    g_cursor[NMAX];
__device__ int    g_csrc[EMAX];        // cols only
__device__ unsigned char g_known[NMAX];
__device__ int    g_bsum[128];
__device__ int    g_boff[128];
__device__ float  g_mean[64];
__device__ float  g_alpha[64];
__device__ float  g_beta[64];
__device__ float  g_colsum[(NUM_ITER + 1) * 64];
__device__ __align__(128) __half2 g_hA[NMAX * HPAD];   // scaled iterate
__device__ __align__(128) __half2 g_hB[NMAX * HPAD];
__device__ float  g_xk[NMAX * DATTR];                  // x - mean (fp32)

// ---- 0) zero per-launch state (graph replays reuse device globals) ----
__global__ void zero_kernel(int n) {
    int i = blockIdx.x * blockDim.x + threadIdx.x;
    if (i < n) { g_deg[i] = 0; g_known[i] = 0; }
    if (i < 64) g_mean[i] = 0.0f;
    if (i < (NUM_ITER + 1) * 64) g_colsum[i] = 0.0f;
}

// ---- 1) out-degree histogram (int4, 4 edges/thread) ----
__global__ void deg_kernel(const int* __restrict__ row, int e) {
    int t = blockIdx.x * blockDim.x + threadIdx.x;
    int j = t * 4;
    if (j + 3 < e) {
        int4 r = __ldg((const int4*)(row + j));
        atomicAdd(&g_deg[r.x], 1);
        atomicAdd(&g_deg[r.y], 1);
        atomicAdd(&g_deg[r.z], 1);
        atomicAdd(&g_deg[r.w], 1);
    } else {
        for (; j < e; j++) atomicAdd(&g_deg[row[j]], 1);
    }
}

// ---- 2) dinv + alpha/beta (entries [d..63] padded to 1.0) ----
__global__ void dinv_alpha_kernel(const float* __restrict__ eta,
                                  const float* __restrict__ theta,
                                  int n, int d) {
    int i = blockIdx.x * blockDim.x + threadIdx.x;
    if (i < n) {
        int dg = g_deg[i];
        g_dinv[i] = (dg > 0) ? rsqrtf((float)dg) : 0.0f;
    }
    if (i < 64) {
        if (i < d) {
            float nf = (float)n;
            float a = (nf - 1.0f) / (theta[i] * nf + (nf - 1.0f));
            g_alpha[i] = a;
            float inva = 1.0f / a;
            g_beta[i] = inva / (inva + eta[i]);
        } else {
            g_alpha[i] = 1.0f;
            g_beta[i] = 1.0f;
        }
    }
}

// ---- 3a) per-block degree sums ----
__global__ void scan_sum_kernel(int n) {
    __shared__ int ssum;
    if (threadIdx.x == 0) ssum = 0;
    __syncthreads();
    int i = blockIdx.x * SCANB + threadIdx.x;
    int v = (i < n) ? g_deg[i] : 0;
    #pragma unroll
    for (int off = 16; off > 0; off >>= 1)
        v += __shfl_down_sync(0xffffffffu, v, off);
    if ((threadIdx.x & 31) == 0) atomicAdd(&ssum, v);
    __syncthreads();
    if (threadIdx.x == 0) g_bsum[blockIdx.x] = ssum;
}

// ---- 3b) scan block sums ----
__global__ void scan_top_kernel(int nb, int n) {
    __shared__ int s[128];
    int t = threadIdx.x;
    int v = (t < nb) ? g_bsum[t] : 0;
    s[t] = v;
    __syncthreads();
    #pragma unroll
    for (int off = 1; off < 128; off <<= 1) {
        int tv = (t >= off) ? s[t - off] : 0;
        __syncthreads();
        s[t] += tv;
        __syncthreads();
    }
    if (t < nb) g_boff[t] = s[t] - v;
    if (t == nb - 1) g_rowptr[n] = s[t];
}

// ---- 3c) per-block exclusive scan + offset ----
__global__ void scan_write_kernel(int n) {
    __shared__ int s[SCANB];
    int tid = threadIdx.x;
    int i = blockIdx.x * SCANB + tid;
    int v = (i < n) ? g_deg[i] : 0;
    s[tid] = v;
    __syncthreads();
    #pragma unroll
    for (int off = 1; off < SCANB; off <<= 1) {
        int tv = (tid >= off) ? s[tid - off] : 0;
        __syncthreads();
        s[tid] += tv;
        __syncthreads();
    }
    if (i < n) {
        int excl = g_boff[blockIdx.x] + s[tid] - v;
        g_rowptr[i] = excl;
        g_cursor[i] = excl;
    }
}

// ---- 4) scatter edge cols into CSR (int4, 4 edges/thread) ----
__global__ void scatter_kernel(const int* __restrict__ row,
                               const int* __restrict__ col, int e) {
    int t = blockIdx.x * blockDim.x + threadIdx.x;
    int j = t * 4;
    if (j + 3 < e) {
        int4 r = __ldg((const int4*)(row + j));
        int4 c = __ldg((const int4*)(col + j));
        g_csrc[atomicAdd(&g_cursor[r.x], 1)] = c.x;
        g_csrc[atomicAdd(&g_cursor[r.y], 1)] = c.y;
        g_csrc[atomicAdd(&g_cursor[r.z], 1)] = c.z;
        g_csrc[atomicAdd(&g_cursor[r.w], 1)] = c.w;
    } else {
        for (; j < e; j++)
            g_csrc[atomicAdd(&g_cursor[row[j]], 1)] = col[j];
    }
}

// ---- 5) known flags + mean sums (duplicates counted) ----
__global__ void mask_mean_kernel(const float* __restrict__ x,
                                 const int* __restrict__ mask, int kcnt) {
    int lane = threadIdx.x & 31;
    int wid = threadIdx.x >> 5;
    int gw = blockIdx.x * (blockDim.x >> 5) + wid;
    int nw = gridDim.x * (blockDim.x >> 5);
    const float2* x2 = (const float2*)x;
    float ax = 0.0f, ay = 0.0f;
    for (int j = gw; j < kcnt; j += nw) {
        int i = mask[j];
        if (lane == 0) g_known[i] = 1;
        if (lane < D2) {
            float2 v = __ldg(&x2[i * D2 + lane]);
            ax += v.x; ay += v.y;
        }
    }
    __shared__ float sm[64];
    if (threadIdx.x < 64) sm[threadIdx.x] = 0.0f;
    __syncthreads();
    if (lane < D2) {
        atomicAdd(&sm[2 * lane], ax);
        atomicAdd(&sm[2 * lane + 1], ay);
    }
    __syncthreads();
    if (threadIdx.x < DATTR) atomicAdd(&g_mean[threadIdx.x], sm[threadIdx.x]);
}

__global__ void mean_div_kernel(int kcnt) {
    if (threadIdx.x < DATTR) g_mean[threadIdx.x] *= (1.0f / (float)kcnt);
}

// ---- 6) xk = x - mean; hA = half(dinv*out0), pad lanes zeroed ----
__global__ void __launch_bounds__(256) init_kernel(const float* __restrict__ x, int n) {
    int lane = threadIdx.x & 31;
    int i = (blockIdx.x * blockDim.x + threadIdx.x) >> 5;
    float vx = 0.0f, vy = 0.0f;
    if (i < n) {
        if (lane < D2) {
            const float2* x2 = (const float2*)x;
            float2 xv = __ldg(&x2[i * D2 + lane]);
            float m0 = g_mean[2 * lane], m1 = g_mean[2 * lane + 1];
            float kx = xv.x - m0, ky = xv.y - m1;
            ((float2*)g_xk)[i * D2 + lane] = make_float2(kx, ky);
            if (g_known[i]) { vx = kx; vy = ky; }
            else            { vx = -m0; vy = -m1; }
            float di = g_dinv[i];
            g_hA[i * HPAD + lane] = __floats2half2_rn(di * vx, di * vy);
        } else {
            g_hA[i * HPAD + lane] = __floats2half2_rn(0.0f, 0.0f);
        }
    }
    __shared__ float sm[64];
    if (threadIdx.x < 64) sm[threadIdx.x] = 0.0f;
    __syncthreads();
    if (i < n && lane < D2) {
        atomicAdd(&sm[2 * lane], vx);
        atomicAdd(&sm[2 * lane + 1], vy);
    }
    __syncthreads();
    if (threadIdx.x < DATTR) atomicAdd(&g_colsum[threadIdx.x], sm[threadIdx.x]);
}

// ---- 7) propagation step: warp/node, unroll-4 pair loop, all-lane gathers ----
__global__ void __launch_bounds__(256) spmm_kernel(
    const __half2* __restrict__ src, __half2* __restrict__ dst,
    float* __restrict__ dout,
    const float* __restrict__ colsum_in, float* __restrict__ colsum_out,
    int n, float inv_n, int final_add_mean) {

    int lane = threadIdx.x & 31;
    int i = (blockIdx.x * blockDim.x + threadIdx.x) >> 5;
    float vx = 0.0f, vy = 0.0f;
    bool valid = (i < n);

    if (valid) {
        float ax = 0.0f, ay = 0.0f;
        int jb = g_rowptr[i], je = g_rowptr[i + 1];
        int j = jb;
        if ((j & 1) && j < je) {              // unaligned head
            int c = __ldg(&g_csrc[j]);
            float2 v = __half22float2(__ldg(&src[c * HPAD + lane]));
            ax += v.x; ay += v.y;
            j++;
        }
        const int2* csr2 = (const int2*)g_csrc;
        int p = j >> 1, pe = je >> 1;
        #pragma unroll 4
        for (; p < pe; p++) {
            int2 c01 = __ldg(&csr2[p]);
            float2 v0 = __half22float2(__ldg(&src[c01.x * HPAD + lane]));
            float2 v1 = __half22float2(__ldg(&src[c01.y * HPAD + lane]));
            ax += v0.x + v1.x;
            ay += v0.y + v1.y;
        }
        j = pe << 1;
        if (j < je) {                          // odd tail
            int c = __ldg(&g_csrc[j]);
            float2 v = __half22float2(__ldg(&src[c * HPAD + lane]));
            ax += v.x; ay += v.y;
        }
        {
            float di = g_dinv[i];
            ax *= di; ay *= di;                // fold dinv[row]
            int d0 = 2 * lane;
            float a0 = g_alpha[d0], a1 = g_alpha[d0 + 1];
            float cm0 = colsum_in[d0] * inv_n;
            float cm1 = colsum_in[d0 + 1] * inv_n;
            vx = a0 * ax + (1.0f - a0) * cm0;
            vy = a1 * ay + (1.0f - a1) * cm1;
            if (g_known[i] && lane < D2) {
                float b0 = g_beta[d0], b1 = g_beta[d0 + 1];
                float2 xk = ((const float2*)g_xk)[i * D2 + lane];
                vx = b0 * vx + (1.0f - b0) * xk.x;
                vy = b1 * vy + (1.0f - b1) * xk.y;
            }
            if (!final_add_mean) {
                // all lanes store: pad lanes write exact zeros
                dst[i * HPAD + lane] = __floats2half2_rn(di * vx, di * vy);
            } else if (lane < D2) {
                float ox = vx + g_mean[d0];
                float oy = vy + g_mean[d0 + 1];
                ((float2*)(dout + i * DATTR))[lane] = make_float2(ox, oy);
            }
        }
    }

    if (!final_add_mean) {
        __shared__ float sm[64];
        if (threadIdx.x < 64) sm[threadIdx.x] = 0.0f;
        __syncthreads();
        if (valid && lane < D2) {
            atomicAdd(&sm[2 * lane], vx);
            atomicAdd(&sm[2 * lane + 1], vy);
        }
        __syncthreads();
        if (threadIdx.x < DATTR)
            atomicAdd(&colsum_out[threadIdx.x], sm[threadIdx.x]);
    }
}

// ---------------------------------------------------------------------------

extern "C" void kernel_launch(void* const* d_in, const int* in_sizes, int n_in,
                              void* d_out, int out_size) {
    const float* x     = (const float*)d_in[0];
    const float* eta   = (const float*)d_in[1];
    const float* theta = (const float*)d_in[2];
    const int*   ei    = (const int*)d_in[3];
    const int*   mask  = (const int*)d_in[4];

    const int D = in_sizes[1];        // 50
    const int n = in_sizes[0] / D;    // 100000
    const int e = in_sizes[3] / 2;    // 1600000
    const int k = in_sizes[4];        // 50000
    const int* row = ei;
    const int* col = ei + e;

    __half2 *hA, *hB;
    float *colsum;
    cudaGetSymbolAddress((void**)&hA, g_hA);
    cudaGetSymbolAddress((void**)&hB, g_hB);
    cudaGetSymbolAddress((void**)&colsum, g_colsum);

    int nb_scan = (n + SCANB - 1) / SCANB;   // 98
    int e4 = (e + 3) / 4;                    // threads for int4 edge kernels

    zero_kernel<<<(n + 255) / 256, 256>>>(n);
    deg_kernel<<<(e4 + 255) / 256, 256>>>(row, e);
    dinv_alpha_kernel<<<(n + 255) / 256, 256>>>(eta, theta, n, D);
    scan_sum_kernel<<<nb_scan, SCANB>>>(n);
    scan_top_kernel<<<1, 128>>>(nb_scan, n);
    scan_write_kernel<<<nb_scan, SCANB>>>(n);
    scatter_kernel<<<(e4 + 255) / 256, 256>>>(row, col, e);
    mask_mean_kernel<<<128, 256>>>(x, mask, k);
    mean_div_kernel<<<1, 64>>>(k);

    int nblocks = (n + WPB - 1) / WPB;
    init_kernel<<<nblocks, 256>>>(x, n);

    float inv_n = 1.0f / (float)n;
    __half2* bufs[2] = { hA, hB };
    for (int t = 0; t < NUM_ITER; t++) {
        const __half2* src = bufs[t & 1];
        int is_final = (t == NUM_ITER - 1);
        __half2* dst = bufs[(t + 1) & 1];
        spmm_kernel<<<nblocks, 256>>>(src, dst, (float*)d_out,
                                      colsum + t * 64, colsum + (t + 1) * 64,
                                      n, inv_n, is_final);
    }
}

// round 17
// speedup vs baseline: 1.0535x; 1.0053x over previous
#include <cuda_runtime.h>
#include <cuda_fp16.h>

// ---------------------------------------------------------------------------
// UMTP propagation, v17 = v14 (1648us verified) + even-padded CSR rows:
// every row's edge segment padded to even length with a dummy col = n whose
// 128B row is all zeros -> spmm gather loop is a pure int2-pair loop, no
// head/tail branches. Dummy gathers hit one L1-resident line (~free).
// ---------------------------------------------------------------------------

#define NMAX     100000
#define EMAX     1700000     // 1.6M edges + <=100K pad entries
#define DATTR    50
#define D2       25          // half2 / float2 data lanes per row
#define HPAD     32          // half2 per padded row (128 bytes)
#define NUM_ITER 30
#define WPB      8
#define SCANB    1024

__device__ int    g_deg[NMAX];
__device__ float  g_dinv[NMAX];
__device__ int    g_rowptr[NMAX + 1];
__device__ int    g_cursor[NMAX];
__device__ int    g_csrc[EMAX];        // cols only (even-padded rows)
__device__ unsigned char g_known[NMAX];
__device__ int    g_bsum[128];
__device__ int    g_boff[128];
__device__ float  g_mean[64];
__device__ float  g_alpha[64];
__device__ float  g_beta[64];
__device__ float  g_colsum[(NUM_ITER + 1) * 64];
__device__ __align__(128) __half2 g_hA[(NMAX + 1) * HPAD];  // +1 dummy zero row
__device__ __align__(128) __half2 g_hB[(NMAX + 1) * HPAD];
__device__ float  g_xk[NMAX * DATTR];                       // x - mean (fp32)

// ---- 0) zero per-launch state; also zero the dummy row n in BOTH buffers ----
__global__ void zero_kernel(int n) {
    int i = blockIdx.x * blockDim.x + threadIdx.x;
    if (i < n) { g_deg[i] = 0; g_known[i] = 0; }
    if (i < 64) g_mean[i] = 0.0f;
    if (i < (NUM_ITER + 1) * 64) g_colsum[i] = 0.0f;
    if (i < HPAD) {
        g_hA[n * HPAD + i] = __floats2half2_rn(0.0f, 0.0f);
        g_hB[n * HPAD + i] = __floats2half2_rn(0.0f, 0.0f);
    }
}

// ---- 1) out-degree histogram (int4, 4 edges/thread) ----
__global__ void deg_kernel(const int* __restrict__ row, int e) {
    int t = blockIdx.x * blockDim.x + threadIdx.x;
    int j = t * 4;
    if (j + 3 < e) {
        int4 r = __ldg((const int4*)(row + j));
        atomicAdd(&g_deg[r.x], 1);
        atomicAdd(&g_deg[r.y], 1);
        atomicAdd(&g_deg[r.z], 1);
        atomicAdd(&g_deg[r.w], 1);
    } else {
        for (; j < e; j++) atomicAdd(&g_deg[row[j]], 1);
    }
}

// ---- 2) dinv + alpha/beta (entries [d..63] padded to 1.0) ----
__global__ void dinv_alpha_kernel(const float* __restrict__ eta,
                                  const float* __restrict__ theta,
                                  int n, int d) {
    int i = blockIdx.x * blockDim.x + threadIdx.x;
    if (i < n) {
        int dg = g_deg[i];
        g_dinv[i] = (dg > 0) ? rsqrtf((float)dg) : 0.0f;
    }
    if (i < 64) {
        if (i < d) {
            float nf = (float)n;
            float a = (nf - 1.0f) / (theta[i] * nf + (nf - 1.0f));
            g_alpha[i] = a;
            float inva = 1.0f / a;
            g_beta[i] = inva / (inva + eta[i]);
        } else {
            g_alpha[i] = 1.0f;
            g_beta[i] = 1.0f;
        }
    }
}

// ---- 3a) per-block PADDED degree sums ----
__global__ void scan_sum_kernel(int n) {
    __shared__ int ssum;
    if (threadIdx.x == 0) ssum = 0;
    __syncthreads();
    int i = blockIdx.x * SCANB + threadIdx.x;
    int v = 0;
    if (i < n) { int dg = g_deg[i]; v = (dg + 1) & ~1; }
    #pragma unroll
    for (int off = 16; off > 0; off >>= 1)
        v += __shfl_down_sync(0xffffffffu, v, off);
    if ((threadIdx.x & 31) == 0) atomicAdd(&ssum, v);
    __syncthreads();
    if (threadIdx.x == 0) g_bsum[blockIdx.x] = ssum;
}

// ---- 3b) scan block sums ----
__global__ void scan_top_kernel(int nb, int n) {
    __shared__ int s[128];
    int t = threadIdx.x;
    int v = (t < nb) ? g_bsum[t] : 0;
    s[t] = v;
    __syncthreads();
    #pragma unroll
    for (int off = 1; off < 128; off <<= 1) {
        int tv = (t >= off) ? s[t - off] : 0;
        __syncthreads();
        s[t] += tv;
        __syncthreads();
    }
    if (t < nb) g_boff[t] = s[t] - v;
    if (t == nb - 1) g_rowptr[n] = s[t];
}

// ---- 3c) per-block exclusive scan (padded) + dummy fill for odd rows ----
__global__ void scan_write_kernel(int n) {
    __shared__ int s[SCANB];
    int tid = threadIdx.x;
    int i = blockIdx.x * SCANB + tid;
    int dg = (i < n) ? g_deg[i] : 0;
    int dp = (dg + 1) & ~1;
    s[tid] = dp;
    __syncthreads();
    #pragma unroll
    for (int off = 1; off < SCANB; off <<= 1) {
        int tv = (tid >= off) ? s[tid - off] : 0;
        __syncthreads();
        s[tid] += tv;
        __syncthreads();
    }
    if (i < n) {
        int excl = g_boff[blockIdx.x] + s[tid] - dp;
        g_rowptr[i] = excl;
        g_cursor[i] = excl;
        if (dg & 1) g_csrc[excl + dg] = n;   // dummy col -> zero row n
    }
}

// ---- 4) scatter edge cols into CSR (int4, 4 edges/thread) ----
__global__ void scatter_kernel(const int* __restrict__ row,
                               const int* __restrict__ col, int e) {
    int t = blockIdx.x * blockDim.x + threadIdx.x;
    int j = t * 4;
    if (j + 3 < e) {
        int4 r = __ldg((const int4*)(row + j));
        int4 c = __ldg((const int4*)(col + j));
        g_csrc[atomicAdd(&g_cursor[r.x], 1)] = c.x;
        g_csrc[atomicAdd(&g_cursor[r.y], 1)] = c.y;
        g_csrc[atomicAdd(&g_cursor[r.z], 1)] = c.z;
        g_csrc[atomicAdd(&g_cursor[r.w], 1)] = c.w;
    } else {
        for (; j < e; j++)
            g_csrc[atomicAdd(&g_cursor[row[j]], 1)] = col[j];
    }
}

// ---- 5) known flags + mean sums (duplicates counted) ----
__global__ void mask_mean_kernel(const float* __restrict__ x,
                                 const int* __restrict__ mask, int kcnt) {
    int lane = threadIdx.x & 31;
    int wid = threadIdx.x >> 5;
    int gw = blockIdx.x * (blockDim.x >> 5) + wid;
    int nw = gridDim.x * (blockDim.x >> 5);
    const float2* x2 = (const float2*)x;
    float ax = 0.0f, ay = 0.0f;
    for (int j = gw; j < kcnt; j += nw) {
        int i = mask[j];
        if (lane == 0) g_known[i] = 1;
        if (lane < D2) {
            float2 v = __ldg(&x2[i * D2 + lane]);
            ax += v.x; ay += v.y;
        }
    }
    __shared__ float sm[64];
    if (threadIdx.x < 64) sm[threadIdx.x] = 0.0f;
    __syncthreads();
    if (lane < D2) {
        atomicAdd(&sm[2 * lane], ax);
        atomicAdd(&sm[2 * lane + 1], ay);
    }
    __syncthreads();
    if (threadIdx.x < DATTR) atomicAdd(&g_mean[threadIdx.x], sm[threadIdx.x]);
}

__global__ void mean_div_kernel(int kcnt) {
    if (threadIdx.x < DATTR) g_mean[threadIdx.x] *= (1.0f / (float)kcnt);
}

// ---- 6) xk = x - mean; hA = half(dinv*out0), pad lanes zeroed ----
__global__ void __launch_bounds__(256) init_kernel(const float* __restrict__ x, int n) {
    int lane = threadIdx.x & 31;
    int i = (blockIdx.x * blockDim.x + threadIdx.x) >> 5;
    float vx = 0.0f, vy = 0.0f;
    if (i < n) {
        if (lane < D2) {
            const float2* x2 = (const float2*)x;
            float2 xv = __ldg(&x2[i * D2 + lane]);
            float m0 = g_mean[2 * lane], m1 = g_mean[2 * lane + 1];
            float kx = xv.x - m0, ky = xv.y - m1;
            ((float2*)g_xk)[i * D2 + lane] = make_float2(kx, ky);
            if (g_known[i]) { vx = kx; vy = ky; }
            else            { vx = -m0; vy = -m1; }
            float di = g_dinv[i];
            g_hA[i * HPAD + lane] = __floats2half2_rn(di * vx, di * vy);
        } else {
            g_hA[i * HPAD + lane] = __floats2half2_rn(0.0f, 0.0f);
        }
    }
    __shared__ float sm[64];
    if (threadIdx.x < 64) sm[threadIdx.x] = 0.0f;
    __syncthreads();
    if (i < n && lane < D2) {
        atomicAdd(&sm[2 * lane], vx);
        atomicAdd(&sm[2 * lane + 1], vy);
    }
    __syncthreads();
    if (threadIdx.x < DATTR) atomicAdd(&g_colsum[threadIdx.x], sm[threadIdx.x]);
}

// ---- 7) propagation step: warp/node, pure pair loop (even-padded rows) ----
__global__ void __launch_bounds__(256) spmm_kernel(
    const __half2* __restrict__ src, __half2* __restrict__ dst,
    float* __restrict__ dout,
    const float* __restrict__ colsum_in, float* __restrict__ colsum_out,
    int n, float inv_n, int final_add_mean) {

    int lane = threadIdx.x & 31;
    int i = (blockIdx.x * blockDim.x + threadIdx.x) >> 5;
    float vx = 0.0f, vy = 0.0f;
    bool valid = (i < n);

    if (valid) {
        float ax = 0.0f, ay = 0.0f;
        int jb = g_rowptr[i], je = g_rowptr[i + 1];
        const int2* csr2 = (const int2*)g_csrc;
        int p = jb >> 1, pe = je >> 1;
        #pragma unroll 4
        for (; p < pe; p++) {
            int2 c01 = __ldg(&csr2[p]);
            float2 v0 = __half22float2(__ldg(&src[c01.x * HPAD + lane]));
            float2 v1 = __half22float2(__ldg(&src[c01.y * HPAD + lane]));
            ax += v0.x + v1.x;
            ay += v0.y + v1.y;
        }
        {
            float di = g_dinv[i];
            ax *= di; ay *= di;                // fold dinv[row]
            int d0 = 2 * lane;
            float a0 = g_alpha[d0], a1 = g_alpha[d0 + 1];
            float cm0 = colsum_in[d0] * inv_n;
            float cm1 = colsum_in[d0 + 1] * inv_n;
            vx = a0 * ax + (1.0f - a0) * cm0;
            vy = a1 * ay + (1.0f - a1) * cm1;
            if (g_known[i] && lane < D2) {
                float b0 = g_beta[d0], b1 = g_beta[d0 + 1];
                float2 xk = ((const float2*)g_xk)[i * D2 + lane];
                vx = b0 * vx + (1.0f - b0) * xk.x;
                vy = b1 * vy + (1.0f - b1) * xk.y;
            }
            if (!final_add_mean) {
                // all lanes store: pad lanes write exact zeros
                dst[i * HPAD + lane] = __floats2half2_rn(di * vx, di * vy);
            } else if (lane < D2) {
                float ox = vx + g_mean[d0];
                float oy = vy + g_mean[d0 + 1];
                ((float2*)(dout + i * DATTR))[lane] = make_float2(ox, oy);
            }
        }
    }

    if (!final_add_mean) {
        __shared__ float sm[64];
        if (threadIdx.x < 64) sm[threadIdx.x] = 0.0f;
        __syncthreads();
        if (valid && lane < D2) {
            atomicAdd(&sm[2 * lane], vx);
            atomicAdd(&sm[2 * lane + 1], vy);
        }
        __syncthreads();
        if (threadIdx.x < DATTR)
            atomicAdd(&colsum_out[threadIdx.x], sm[threadIdx.x]);
    }
}

// ---------------------------------------------------------------------------

extern "C" void kernel_launch(void* const* d_in, const int* in_sizes, int n_in,
                              void* d_out, int out_size) {
    const float* x     = (const float*)d_in[0];
    const float* eta   = (const float*)d_in[1];
    const float* theta = (const float*)d_in[2];
    const int*   ei    = (const int*)d_in[3];
    const int*   mask  = (const int*)d_in[4];

    const int D = in_sizes[1];        // 50
    const int n = in_sizes[0] / D;    // 100000
    const int e = in_sizes[3] / 2;    // 1600000
    const int k = in_sizes[4];        // 50000
    const int* row = ei;
    const int* col = ei + e;

    __half2 *hA, *hB;
    float *colsum;
    cudaGetSymbolAddress((void**)&hA, g_hA);
    cudaGetSymbolAddress((void**)&hB, g_hB);
    cudaGetSymbolAddress((void**)&colsum, g_colsum);

    int nb_scan = (n + SCANB - 1) / SCANB;   // 98
    int e4 = (e + 3) / 4;                    // threads for int4 edge kernels

    zero_kernel<<<(n + 255) / 256, 256>>>(n);
    deg_kernel<<<(e4 + 255) / 256, 256>>>(row, e);
    dinv_alpha_kernel<<<(n + 255) / 256, 256>>>(eta, theta, n, D);
    scan_sum_kernel<<<nb_scan, SCANB>>>(n);
    scan_top_kernel<<<1, 128>>>(nb_scan, n);
    scan_write_kernel<<<nb_scan, SCANB>>>(n);
    scatter_kernel<<<(e4 + 255) / 256, 256>>>(row, col, e);
    mask_mean_kernel<<<128, 256>>>(x, mask, k);
    mean_div_kernel<<<1, 64>>>(k);

    int nblocks = (n + WPB - 1) / WPB;
    init_kernel<<<nblocks, 256>>>(x, n);

    float inv_n = 1.0f / (float)n;
    __half2* bufs[2] = { hA, hB };
    for (int t = 0; t < NUM_ITER; t++) {
        const __half2* src = bufs[t & 1];
        int is_final = (t == NUM_ITER - 1);
        __half2* dst = bufs[(t + 1) & 1];
        spmm_kernel<<<nblocks, 256>>>(src, dst, (float*)d_out,
                                      colsum + t * 64, colsum + (t + 1) * 64,
                                      n, inv_n, is_final);
    }
}